// round 15
// baseline (speedup 1.0000x reference)
#include <cuda_runtime.h>
#include <cuda_bf16.h>
#include <math_constants.h>
#include <stdint.h>

// Problem constants
#define B_SZ 4
#define S_SZ 4096
#define E_SZ 1024
#define H_SZ 16
#define HD_SZ 64
#define W_SZ 128
#define NW_SZ 32
#define BH_SZ (B_SZ * H_SZ)      // 64
#define M_GEMM (B_SZ * S_SZ)     // 16384
#define N_GEMM (3 * E_SZ)        // 3072
#define K_GEMM E_SZ              // 1024
#define LOG2E 1.44269504088896340736f

// GEMM input splits. A: [M,K] K-major. W: [K,N] row-major.
__device__ __nv_bfloat16 g_Ahi[M_GEMM * K_GEMM];
__device__ __nv_bfloat16 g_Alo[M_GEMM * K_GEMM];
__device__ __nv_bfloat16 g_Whi[K_GEMM * N_GEMM];
__device__ __nv_bfloat16 g_Wlo[K_GEMM * N_GEMM];
// q/k/v head layout [BH, S, HD], bf16 hi/lo.  NOTE: q is pre-scaled by log2(e).
__device__ __nv_bfloat16 g_qhi[BH_SZ * S_SZ * HD_SZ];
__device__ __nv_bfloat16 g_qlo[BH_SZ * S_SZ * HD_SZ];
__device__ __nv_bfloat16 g_khi[BH_SZ * S_SZ * HD_SZ];
__device__ __nv_bfloat16 g_klo[BH_SZ * S_SZ * HD_SZ];
__device__ __nv_bfloat16 g_vhi[BH_SZ * S_SZ * HD_SZ];
__device__ __nv_bfloat16 g_vlo[BH_SZ * S_SZ * HD_SZ];

// ---------------------------------------------------------------------------
// helpers
// ---------------------------------------------------------------------------
__device__ __forceinline__ void split2(float x, float y, uint32_t& hi, uint32_t& lo)
{
    __nv_bfloat16 hx = __float2bfloat16(x);
    __nv_bfloat16 hy = __float2bfloat16(y);
    float rx = x - __bfloat162float(hx);
    float ry = y - __bfloat162float(hy);
    __nv_bfloat162 h; h.x = hx; h.y = hy;
    __nv_bfloat162 l; l.x = __float2bfloat16(rx); l.y = __float2bfloat16(ry);
    hi = *reinterpret_cast<uint32_t*>(&h);
    lo = *reinterpret_cast<uint32_t*>(&l);
}

__device__ __forceinline__ uint32_t smem_u32(const void* p)
{
    return (uint32_t)__cvta_generic_to_shared(p);
}

__device__ __forceinline__ float ex2(float x)
{
    float r;
    asm("ex2.approx.f32 %0, %1;" : "=f"(r) : "f"(x));
    return r;
}

__device__ __forceinline__ float rcp(float x)
{
    float r;
    asm("rcp.approx.f32 %0, %1;" : "=f"(r) : "f"(x));
    return r;
}

#define CP_ASYNC16(dst_u32, src_ptr)                                            \
    asm volatile("cp.async.cg.shared.global [%0], [%1], 16;\n"                  \
                 :: "r"(dst_u32), "l"(__cvta_generic_to_global(src_ptr)))
#define CP_COMMIT() asm volatile("cp.async.commit_group;\n" ::)
#define CP_WAIT1()  asm volatile("cp.async.wait_group 1;\n" ::)
#define CP_WAIT0()  asm volatile("cp.async.wait_group 0;\n" ::)

#define LDSM4(R, ADDR)                                                          \
    asm volatile("ldmatrix.sync.aligned.m8n8.x4.shared.b16 {%0,%1,%2,%3}, [%4];"\
                 : "=r"(R[0]), "=r"(R[1]), "=r"(R[2]), "=r"(R[3]) : "r"(ADDR))
#define LDSM4T(R0, R1, R2, R3, ADDR)                                            \
    asm volatile("ldmatrix.sync.aligned.m8n8.x4.trans.shared.b16 {%0,%1,%2,%3}, [%4];" \
                 : "=r"(R0), "=r"(R1), "=r"(R2), "=r"(R3) : "r"(ADDR))

#define MMA16816(ACC, A0, A1, A2, A3, B0, B1)                                   \
    asm volatile(                                                               \
        "mma.sync.aligned.m16n8k16.row.col.f32.bf16.bf16.f32 "                  \
        "{%0,%1,%2,%3}, {%4,%5,%6,%7}, {%8,%9}, {%0,%1,%2,%3};\n"               \
        : "+f"(ACC[0]), "+f"(ACC[1]), "+f"(ACC[2]), "+f"(ACC[3])                \
        : "r"(A0), "r"(A1), "r"(A2), "r"(A3), "r"(B0), "r"(B1))

// ---------------------------------------------------------------------------
// Kernel 0: fused fp32 -> bf16 hi/lo splits for A and W (one launch).
// 8 elements per thread (at HBM roofline — unchanged).
// ---------------------------------------------------------------------------
#define A_SPLIT_BLOCKS (M_GEMM * K_GEMM / 8 / 256)   // 8192
#define W_SPLIT_BLOCKS (K_GEMM * N_GEMM / 8 / 256)   // 1536

__global__ __launch_bounds__(256)
void split_all_kernel(const float* __restrict__ x, const float* __restrict__ w)
{
    const int bid = blockIdx.x;
    const float* src;
    __nv_bfloat16 *hi, *lo;
    int i;
    if (bid < A_SPLIT_BLOCKS) {
        src = x; hi = g_Ahi; lo = g_Alo;
        i = (bid * 256 + threadIdx.x) * 8;
    } else {
        src = w; hi = g_Whi; lo = g_Wlo;
        i = ((bid - A_SPLIT_BLOCKS) * 256 + threadIdx.x) * 8;
    }
    float4 v0 = *(const float4*)(src + i);
    float4 v1 = *(const float4*)(src + i + 4);
    uint4 hh, ll;
    split2(v0.x, v0.y, hh.x, ll.x);
    split2(v0.z, v0.w, hh.y, ll.y);
    split2(v1.x, v1.y, hh.z, ll.z);
    split2(v1.z, v1.w, hh.w, ll.w);
    *(uint4*)(hi + i) = hh;
    *(uint4*)(lo + i) = ll;
}

// ---------------------------------------------------------------------------
// Kernel 1: QKV GEMM, bf16x3 HMMA, BK=32, 3-stage pipeline, 2 CTAs/SM.
// Epilogue scales the q output by log2(e) so attention can use exp2 directly.
// ---------------------------------------------------------------------------
#define S_ALO 8192
#define S_WHI 16384
#define S_WLO 24576
#define STAGE_B 32768
#define NST 3
#define GEMM_SMEM (NST * STAGE_B)   // 98304 -> 2 CTAs/SM
#define NIT (K_GEMM / 32)           // 32
#define EP_PITCH 68                 // u32 pitch for epilogue planes

__global__ __launch_bounds__(256, 2)
void qkv_gemm_tc(const float* __restrict__ bias)
{
    extern __shared__ char smb[];

    const int t    = threadIdx.x;
    const int bm   = blockIdx.y * 128;
    const int bn   = blockIdx.x * 128;
    const int lane = t & 31;
    const int wid  = t >> 5;
    const int g    = lane >> 2;
    const int t4   = lane & 3;
    const int m0   = (wid >> 1) * 32;
    const int wn   = wid & 1;
    const int n0   = wn * 64;

    float acc[2][8][4];
#pragma unroll
    for (int mt = 0; mt < 2; ++mt)
#pragma unroll
        for (int nt = 0; nt < 8; ++nt)
#pragma unroll
            for (int r = 0; r < 4; ++r) acc[mt][nt][r] = 0.f;

    auto issue = [&](int kt, int buf) {
        char* base = smb + buf * STAGE_B;
        const int k0 = kt * 32;
#pragma unroll
        for (int i = 0; i < 2; ++i) {                  // A hi/lo: 128 rows x 4 chunks
            const int id   = t + 256 * i;
            const int row  = id >> 2;
            const int c    = id & 3;
            const int srow = row & 63;
            const int ch   = (c + ((row >> 6) << 2)) ^ (srow & 7);
            const uint32_t doff = (uint32_t)(srow * 128 + ch * 16);
            const size_t  soff = (size_t)(bm + row) * K_GEMM + k0 + c * 8;
            CP_ASYNC16(smem_u32(base + doff), g_Ahi + soff);
            CP_ASYNC16(smem_u32(base + S_ALO + doff), g_Alo + soff);
        }
#pragma unroll
        for (int i = 0; i < 2; ++i) {                  // W hi/lo: 32 rows x 16 chunks
            const int id  = t + 256 * i;
            const int row = id >> 4;
            const int c   = id & 15;
            const uint32_t doff = (uint32_t)(row * 256 + ((c ^ (row & 7)) * 16));
            const size_t  soff = (size_t)(k0 + row) * N_GEMM + bn + c * 8;
            CP_ASYNC16(smem_u32(base + S_WHI + doff), g_Whi + soff);
            CP_ASYNC16(smem_u32(base + S_WLO + doff), g_Wlo + soff);
        }
    };

    issue(0, 0); CP_COMMIT();
    issue(1, 1); CP_COMMIT();

    for (int it = 0; it < NIT; ++it) {
        CP_WAIT1();
        __syncthreads();
        if (it + 2 < NIT) issue(it + 2, (it + 2) % NST);
        CP_COMMIT();

        const char* base = smb + (it % NST) * STAGE_B;
        const uint32_t aAhi = smem_u32(base);
        const uint32_t aAlo = smem_u32(base + S_ALO);
        const uint32_t aWhi = smem_u32(base + S_WHI);
        const uint32_t aWlo = smem_u32(base + S_WLO);

#pragma unroll
        for (int kk = 0; kk < 2; ++kk) {
            uint32_t aF[2][2][4];
            {
                const int mrow  = m0 + (lane & 15);
                const int srow0 = mrow & 63;
                const int hb    = (mrow >> 6) << 2;
                const int cb    = hb + 2 * kk + (lane >> 4);
                const uint32_t off0 = (uint32_t)(srow0 * 128 + ((cb ^ (srow0 & 7)) * 16));
                const int srow1 = (mrow + 16) & 63;
                const uint32_t off1 = (uint32_t)(srow1 * 128 + ((cb ^ (srow1 & 7)) * 16));
                LDSM4(aF[0][0], aAhi + off0);
                LDSM4(aF[0][1], aAhi + off1);
                LDSM4(aF[1][0], aAlo + off0);
                LDSM4(aF[1][1], aAlo + off1);
            }

            const int krow = kk * 16 + (lane & 15);
            const uint32_t wrow_off = (uint32_t)(krow * 256);
            const int bsel = lane >> 4;

#pragma unroll
            for (int nh = 0; nh < 2; ++nh) {
                uint32_t bF[2][4][2];
#pragma unroll
                for (int p = 0; p < 2; ++p) {
                    const int cc = wn * 8 + nh * 4 + 2 * p + bsel;
                    const uint32_t off = wrow_off + (uint32_t)((cc ^ (krow & 7)) * 16);
                    LDSM4T(bF[0][2 * p][0], bF[0][2 * p][1],
                           bF[0][2 * p + 1][0], bF[0][2 * p + 1][1], aWhi + off);
                    LDSM4T(bF[1][2 * p][0], bF[1][2 * p][1],
                           bF[1][2 * p + 1][0], bF[1][2 * p + 1][1], aWlo + off);
                }

#pragma unroll
                for (int nt = 0; nt < 4; ++nt)
#pragma unroll
                    for (int mt = 0; mt < 2; ++mt)
                        MMA16816(acc[mt][nh * 4 + nt],
                                 aF[0][mt][0], aF[0][mt][1], aF[0][mt][2], aF[0][mt][3],
                                 bF[0][nt][0], bF[0][nt][1]);
#pragma unroll
                for (int nt = 0; nt < 4; ++nt)
#pragma unroll
                    for (int mt = 0; mt < 2; ++mt)
                        MMA16816(acc[mt][nh * 4 + nt],
                                 aF[0][mt][0], aF[0][mt][1], aF[0][mt][2], aF[0][mt][3],
                                 bF[1][nt][0], bF[1][nt][1]);
#pragma unroll
                for (int nt = 0; nt < 4; ++nt)
#pragma unroll
                    for (int mt = 0; mt < 2; ++mt)
                        MMA16816(acc[mt][nh * 4 + nt],
                                 aF[1][mt][0], aF[1][mt][1], aF[1][mt][2], aF[1][mt][3],
                                 bF[0][nt][0], bF[0][nt][1]);
            }
        }
    }

    // ---- epilogue: bias (+ log2e scale for q) + split -> smem -> 16B stores
    CP_WAIT0();
    __syncthreads();

    const int which = bn >> 10;                      // CTA-uniform
    const float qscale = (which == 0) ? LOG2E : 1.0f;

    uint32_t* shi = (uint32_t*)smb;                 // 128 x EP_PITCH u32
    uint32_t* slo = shi + 128 * EP_PITCH;

#pragma unroll
    for (int mt = 0; mt < 2; ++mt) {
#pragma unroll
        for (int nt = 0; nt < 8; ++nt) {
            const int cc = bn + n0 + nt * 8 + 2 * t4;
            const float bx = __ldg(bias + cc);
            const float by = __ldg(bias + cc + 1);
            const int cidx = (n0 >> 1) + nt * 4 + t4;   // u32 column 0..63
#pragma unroll
            for (int half = 0; half < 2; ++half) {
                const int srow = m0 + mt * 16 + g + half * 8;
                uint32_t hv, lv;
                split2((acc[mt][nt][2 * half] + bx) * qscale,
                       (acc[mt][nt][2 * half + 1] + by) * qscale, hv, lv);
                shi[srow * EP_PITCH + cidx] = hv;
                slo[srow * EP_PITCH + cidx] = lv;
            }
        }
    }
    __syncthreads();

    __nv_bfloat16* dhi = (which == 0) ? g_qhi : (which == 1) ? g_khi : g_vhi;
    __nv_bfloat16* dlo = (which == 0) ? g_qlo : (which == 1) ? g_klo : g_vlo;

#pragma unroll
    for (int i = 0; i < 8; ++i) {
        const int u   = t + 256 * i;       // uint4 index 0..2047
        const int row = u >> 4;            // 0..127
        const int cu  = u & 15;            // 16B chunk within row
        uint4 vh = *(uint4*)(shi + row * EP_PITCH + cu * 4);
        uint4 vl = *(uint4*)(slo + row * EP_PITCH + cu * 4);
        const int mg = bm + row;
        const int b  = mg >> 12;
        const int s  = mg & 4095;
        const int n  = bn + cu * 8;
        const int h  = (n & 1023) >> 6;
        const int d0 = n & 63;
        const size_t off = ((size_t)(b * H_SZ + h) * S_SZ + s) * HD_SZ + d0;
        *(uint4*)(dhi + off) = vh;
        *(uint4*)(dlo + off) = vl;
    }
}

// ---------------------------------------------------------------------------
// Kernel 2: MMA flash attention, fixed-max softmax in exp2 domain.
// ex2.approx / rcp.approx via inline asm; qsum only on boundary windows;
// mask chain skipped for own-window chunk.
// ---------------------------------------------------------------------------
#define SQ_HI 0
#define SQ_LO 16384
#define SK_HI 32768
#define SV_HI 65536
#define S_QSUM 98304
#define ATT_SMEM (98304 + 512)
#define MFIX2 (24.0f * 1.44269504088896340736f)   // 24 * log2(e)

__global__ __launch_bounds__(256, 2)
void attn_mma(float* __restrict__ out)
{
    extern __shared__ char smb[];
    const int w    = blockIdx.x;
    const int bh   = blockIdx.y;
    const int t    = threadIdx.x;
    const int lane = t & 31;
    const int wid  = t >> 5;
    const int g    = lane >> 2;
    const int t4   = lane & 3;
    const int r0   = wid * 16;
    const bool haspad = (w == 0) || (w == NW_SZ - 1);   // block-uniform

#pragma unroll
    for (int i = 0; i < 8; ++i) {
        const int id  = t + 256 * i;
        const int buf = id >> 10;
        const int idx = id & 1023;
        const int row = idx >> 3;
        const int c   = idx & 7;
        const int ph  = c ^ (row & 7);
        const __nv_bfloat16* src = buf ? g_qlo : g_qhi;
        CP_ASYNC16(smem_u32(smb + buf * 16384 + row * 128 + ph * 16),
                   src + ((size_t)bh * S_SZ + w * W_SZ + row) * HD_SZ + c * 8);
    }
    CP_COMMIT(); CP_WAIT0();
    __syncthreads();

    float* qsum = (float*)(smb + S_QSUM);
    if (haspad) {                       // qsum needed only for boundary windows
        if (t < 128) {
            float s = 0.f;
#pragma unroll
            for (int c = 0; c < 8; ++c) {
                const int ph = c ^ (t & 7);
                const uint32_t* hp = (const uint32_t*)(smb + SQ_HI + t * 128 + ph * 16);
                const uint32_t* lp = (const uint32_t*)(smb + SQ_LO + t * 128 + ph * 16);
#pragma unroll
                for (int e = 0; e < 4; ++e) {
                    float2 fh = __bfloat1622float2(*(const __nv_bfloat162*)&hp[e]);
                    float2 fl = __bfloat1622float2(*(const __nv_bfloat162*)&lp[e]);
                    s += fh.x + fh.y + fl.x + fl.y;
                }
            }
            qsum[t] = s;   // already in log2 domain (q pre-scaled)
        }
        __syncthreads();
    }

    float l0 = 0.f, l1 = 0.f;        // per-lane partial row sums
    float O[8][4];
#pragma unroll
    for (int nd = 0; nd < 8; ++nd)
#pragma unroll
        for (int r = 0; r < 4; ++r) O[nd][r] = 0.f;

#pragma unroll
    for (int c = 0; c < 3; ++c) {
        const int wc = w - 1 + c;
        if (wc < 0 || wc >= NW_SZ) {
            const float e0 = ex2(-qsum[r0 + g]     - MFIX2);
            const float e1 = ex2(-qsum[r0 + g + 8] - MFIX2);
            l0 += e0 * 32.f;
            l1 += e1 * 32.f;
            const float q0 = e0 * 128.f;
            const float q1 = e1 * 128.f;
#pragma unroll
            for (int nd = 0; nd < 8; ++nd) {
                O[nd][0] -= q0; O[nd][1] -= q0;
                O[nd][2] -= q1; O[nd][3] -= q1;
            }
            continue;
        }

        __syncthreads();
#pragma unroll
        for (int i = 0; i < 16; ++i) {
            const int id  = t + 256 * i;
            const int buf = id >> 10;
            const int idx = id & 1023;
            const int row = idx >> 3;
            const int cc  = idx & 7;
            const int ph  = cc ^ (row & 7);
            const __nv_bfloat16* src = (buf == 0) ? g_khi : (buf == 1) ? g_klo
                                      : (buf == 2) ? g_vhi : g_vlo;
            CP_ASYNC16(smem_u32(smb + SK_HI + buf * 16384 + row * 128 + ph * 16),
                       src + ((size_t)bh * S_SZ + wc * W_SZ + row) * HD_SZ + cc * 8);
        }
        CP_COMMIT(); CP_WAIT0();
        __syncthreads();

        const int type = c;

#pragma unroll
        for (int half = 0; half < 2; ++half) {
            const int kb = 64 * half;
            int pmin = 0, pmax = 3;
            if (type == 0) {
                int d = r0 - kb; if (d < 0) d = 0;
                pmin = d >> 4;
                if (pmin > 3) continue;
            } else if (type == 2) {
                const int d = r0 - kb + 15;
                if (d < 0) continue;
                pmax = d >> 4; if (pmax > 3) pmax = 3;
            }

            float S[8][4];
#pragma unroll
            for (int j = 0; j < 8; ++j)
#pragma unroll
                for (int r = 0; r < 4; ++r) S[j][r] = 0.f;

#pragma unroll
            for (int ks = 0; ks < 4; ++ks) {
                uint32_t qh[4], ql[4];
                {
                    const int row = r0 + (lane & 15);
                    const int cc  = 2 * ks + (lane >> 4);
                    const int ph  = cc ^ (row & 7);
                    const uint32_t aq = smem_u32(smb + SQ_HI + row * 128 + ph * 16);
                    LDSM4(qh, aq);
                    LDSM4(ql, aq + 16384);
                }
#pragma unroll
                for (int p = 0; p < 4; ++p) {
                    if (p < pmin || p > pmax) continue;
                    uint32_t kh[4], kl[4];
                    {
                        const int row = kb + 16 * p + (lane & 7) + ((lane >> 4) << 3);
                        const int cc  = 2 * ks + ((lane >> 3) & 1);
                        const int ph  = cc ^ (row & 7);
                        const uint32_t ak = smem_u32(smb + SK_HI + row * 128 + ph * 16);
                        LDSM4(kh, ak);
                        LDSM4(kl, ak + 16384);
                    }
                    MMA16816(S[2 * p],     qh[0], qh[1], qh[2], qh[3], kh[0], kh[1]);
                    MMA16816(S[2 * p],     qh[0], qh[1], qh[2], qh[3], kl[0], kl[1]);
                    MMA16816(S[2 * p],     ql[0], ql[1], ql[2], ql[3], kh[0], kh[1]);
                    MMA16816(S[2 * p + 1], qh[0], qh[1], qh[2], qh[3], kh[2], kh[3]);
                    MMA16816(S[2 * p + 1], qh[0], qh[1], qh[2], qh[3], kl[2], kl[3]);
                    MMA16816(S[2 * p + 1], ql[0], ql[1], ql[2], ql[3], kh[2], kh[3]);
                }
            }

            // mask (skipped entirely for the own-window chunk)
            if (type != 1) {
#pragma unroll
                for (int j = 0; j < 8; ++j) {
                    if ((j >> 1) < pmin || (j >> 1) > pmax) continue;
#pragma unroll
                    for (int e = 0; e < 2; ++e) {
                        const int key = kb + 8 * j + 2 * t4 + e;
                        if (type == 0) {
                            if (key < r0 + g)     S[j][e]     = -CUDART_INF_F;
                            if (key < r0 + g + 8) S[j][2 + e] = -CUDART_INF_F;
                        } else {
                            if (key > r0 + g)     S[j][e]     = -CUDART_INF_F;
                            if (key > r0 + g + 8) S[j][2 + e] = -CUDART_INF_F;
                        }
                    }
                }
            }
            // exp2(s - MFIX2) + per-lane partial l
#pragma unroll
            for (int j = 0; j < 8; ++j) {
                if ((j >> 1) < pmin || (j >> 1) > pmax) continue;
#pragma unroll
                for (int e = 0; e < 2; ++e) {
                    S[j][e]     = ex2(S[j][e]     - MFIX2); l0 += S[j][e];
                    S[j][2 + e] = ex2(S[j][2 + e] - MFIX2); l1 += S[j][2 + e];
                }
            }

            // O += P V (bf16x3)
#pragma unroll
            for (int kt = 0; kt < 4; ++kt) {
                if (kt < pmin || kt > pmax) continue;
                uint32_t pah[4], pal[4];
                split2(S[2 * kt][0],     S[2 * kt][1],     pah[0], pal[0]);
                split2(S[2 * kt][2],     S[2 * kt][3],     pah[1], pal[1]);
                split2(S[2 * kt + 1][0], S[2 * kt + 1][1], pah[2], pal[2]);
                split2(S[2 * kt + 1][2], S[2 * kt + 1][3], pah[3], pal[3]);
#pragma unroll
                for (int dp = 0; dp < 4; ++dp) {
                    uint32_t vh[4], vl[4];
                    {
                        const int krow = kb + 16 * kt + (lane & 15);
                        const int cc   = 2 * dp + (lane >> 4);
                        const int ph   = cc ^ (krow & 7);
                        const uint32_t av = smem_u32(smb + SV_HI + krow * 128 + ph * 16);
                        LDSM4T(vh[0], vh[1], vh[2], vh[3], av);
                        LDSM4T(vl[0], vl[1], vl[2], vl[3], av + 16384);
                    }
                    MMA16816(O[2 * dp],     pah[0], pah[1], pah[2], pah[3], vh[0], vh[1]);
                    MMA16816(O[2 * dp],     pah[0], pah[1], pah[2], pah[3], vl[0], vl[1]);
                    MMA16816(O[2 * dp],     pal[0], pal[1], pal[2], pal[3], vh[0], vh[1]);
                    MMA16816(O[2 * dp + 1], pah[0], pah[1], pah[2], pah[3], vh[2], vh[3]);
                    MMA16816(O[2 * dp + 1], pah[0], pah[1], pah[2], pah[3], vl[2], vl[3]);
                    MMA16816(O[2 * dp + 1], pal[0], pal[1], pal[2], pal[3], vh[2], vh[3]);
                }
            }
        }
    }

    // reduce l over the t4 quad, normalize (rcp.approx), write out
    l0 += __shfl_xor_sync(0xffffffffu, l0, 1);
    l0 += __shfl_xor_sync(0xffffffffu, l0, 2);
    l1 += __shfl_xor_sync(0xffffffffu, l1, 1);
    l1 += __shfl_xor_sync(0xffffffffu, l1, 2);

    const float inv0 = rcp(l0), inv1 = rcp(l1);
    const int b = bh >> 4, h = bh & 15;
    const int row0 = w * W_SZ + r0 + g;
    float* o0 = out + ((size_t)b * S_SZ + row0) * E_SZ + h * HD_SZ + 2 * t4;
    float* o1 = out + ((size_t)b * S_SZ + row0 + 8) * E_SZ + h * HD_SZ + 2 * t4;
#pragma unroll
    for (int nd = 0; nd < 8; ++nd) {
        float2 u; u.x = O[nd][0] * inv0; u.y = O[nd][1] * inv0;
        *(float2*)(o0 + 8 * nd) = u;
        float2 v; v.x = O[nd][2] * inv1; v.y = O[nd][3] * inv1;
        *(float2*)(o1 + 8 * nd) = v;
    }
}

// ---------------------------------------------------------------------------
extern "C" void kernel_launch(void* const* d_in, const int* in_sizes, int n_in,
                              void* d_out, int out_size)
{
    const float* x    = (const float*)d_in[0];   // [4, 4096, 1024]
    const float* wqkv = (const float*)d_in[1];   // [1024, 3072]
    const float* bqkv = (const float*)d_in[2];   // [3072]
    float* out = (float*)d_out;                  // [4, 4096, 1024]

    split_all_kernel<<<A_SPLIT_BLOCKS + W_SPLIT_BLOCKS, 256>>>(x, wqkv);

    cudaFuncSetAttribute(qkv_gemm_tc,
                         cudaFuncAttributeMaxDynamicSharedMemorySize, GEMM_SMEM);
    dim3 g1(N_GEMM / 128, M_GEMM / 128);         // (24, 128)
    qkv_gemm_tc<<<g1, 256, GEMM_SMEM>>>(bqkv);

    cudaFuncSetAttribute(attn_mma,
                         cudaFuncAttributeMaxDynamicSharedMemorySize, ATT_SMEM);
    dim3 g2(NW_SZ, BH_SZ);                       // (32, 64)
    attn_mma<<<g2, 256, ATT_SMEM>>>(out);
}

// round 16
// speedup vs baseline: 1.0003x; 1.0003x over previous
#include <cuda_runtime.h>
#include <cuda_bf16.h>
#include <math_constants.h>
#include <stdint.h>

// Problem constants
#define B_SZ 4
#define S_SZ 4096
#define E_SZ 1024
#define H_SZ 16
#define HD_SZ 64
#define W_SZ 128
#define NW_SZ 32
#define BH_SZ (B_SZ * H_SZ)      // 64
#define M_GEMM (B_SZ * S_SZ)     // 16384
#define N_GEMM (3 * E_SZ)        // 3072
#define K_GEMM E_SZ              // 1024
#define LOG2E 1.44269504088896340736f

// GEMM input splits. A: [M,K] K-major. W: [K,N] row-major.
__device__ __nv_bfloat16 g_Ahi[M_GEMM * K_GEMM];
__device__ __nv_bfloat16 g_Alo[M_GEMM * K_GEMM];
__device__ __nv_bfloat16 g_Whi[K_GEMM * N_GEMM];
__device__ __nv_bfloat16 g_Wlo[K_GEMM * N_GEMM];
// q/k/v head layout [BH, S, HD], bf16 hi/lo.  NOTE: q is pre-scaled by log2(e).
__device__ __nv_bfloat16 g_qhi[BH_SZ * S_SZ * HD_SZ];
__device__ __nv_bfloat16 g_qlo[BH_SZ * S_SZ * HD_SZ];
__device__ __nv_bfloat16 g_khi[BH_SZ * S_SZ * HD_SZ];
__device__ __nv_bfloat16 g_klo[BH_SZ * S_SZ * HD_SZ];
__device__ __nv_bfloat16 g_vhi[BH_SZ * S_SZ * HD_SZ];
__device__ __nv_bfloat16 g_vlo[BH_SZ * S_SZ * HD_SZ];

// ---------------------------------------------------------------------------
// helpers
// ---------------------------------------------------------------------------
__device__ __forceinline__ void split2(float x, float y, uint32_t& hi, uint32_t& lo)
{
    __nv_bfloat16 hx = __float2bfloat16(x);
    __nv_bfloat16 hy = __float2bfloat16(y);
    float rx = x - __bfloat162float(hx);
    float ry = y - __bfloat162float(hy);
    __nv_bfloat162 h; h.x = hx; h.y = hy;
    __nv_bfloat162 l; l.x = __float2bfloat16(rx); l.y = __float2bfloat16(ry);
    hi = *reinterpret_cast<uint32_t*>(&h);
    lo = *reinterpret_cast<uint32_t*>(&l);
}

__device__ __forceinline__ uint32_t smem_u32(const void* p)
{
    return (uint32_t)__cvta_generic_to_shared(p);
}

#define CP_ASYNC16(dst_u32, src_ptr)                                            \
    asm volatile("cp.async.cg.shared.global [%0], [%1], 16;\n"                  \
                 :: "r"(dst_u32), "l"(__cvta_generic_to_global(src_ptr)))
#define CP_COMMIT() asm volatile("cp.async.commit_group;\n" ::)
#define CP_WAIT1()  asm volatile("cp.async.wait_group 1;\n" ::)
#define CP_WAIT0()  asm volatile("cp.async.wait_group 0;\n" ::)

#define LDSM4(R, ADDR)                                                          \
    asm volatile("ldmatrix.sync.aligned.m8n8.x4.shared.b16 {%0,%1,%2,%3}, [%4];"\
                 : "=r"(R[0]), "=r"(R[1]), "=r"(R[2]), "=r"(R[3]) : "r"(ADDR))
#define LDSM4T(R0, R1, R2, R3, ADDR)                                            \
    asm volatile("ldmatrix.sync.aligned.m8n8.x4.trans.shared.b16 {%0,%1,%2,%3}, [%4];" \
                 : "=r"(R0), "=r"(R1), "=r"(R2), "=r"(R3) : "r"(ADDR))

#define MMA16816(ACC, A0, A1, A2, A3, B0, B1)                                   \
    asm volatile(                                                               \
        "mma.sync.aligned.m16n8k16.row.col.f32.bf16.bf16.f32 "                  \
        "{%0,%1,%2,%3}, {%4,%5,%6,%7}, {%8,%9}, {%0,%1,%2,%3};\n"               \
        : "+f"(ACC[0]), "+f"(ACC[1]), "+f"(ACC[2]), "+f"(ACC[3])                \
        : "r"(A0), "r"(A1), "r"(A2), "r"(A3), "r"(B0), "r"(B1))

// ---------------------------------------------------------------------------
// Kernel 0: fused fp32 -> bf16 hi/lo splits for A and W (one launch).
// 8 elements per thread (at HBM roofline — unchanged).
// ---------------------------------------------------------------------------
#define A_SPLIT_BLOCKS (M_GEMM * K_GEMM / 8 / 256)   // 8192
#define W_SPLIT_BLOCKS (K_GEMM * N_GEMM / 8 / 256)   // 1536

__global__ __launch_bounds__(256)
void split_all_kernel(const float* __restrict__ x, const float* __restrict__ w)
{
    const int bid = blockIdx.x;
    const float* src;
    __nv_bfloat16 *hi, *lo;
    int i;
    if (bid < A_SPLIT_BLOCKS) {
        src = x; hi = g_Ahi; lo = g_Alo;
        i = (bid * 256 + threadIdx.x) * 8;
    } else {
        src = w; hi = g_Whi; lo = g_Wlo;
        i = ((bid - A_SPLIT_BLOCKS) * 256 + threadIdx.x) * 8;
    }
    float4 v0 = *(const float4*)(src + i);
    float4 v1 = *(const float4*)(src + i + 4);
    uint4 hh, ll;
    split2(v0.x, v0.y, hh.x, ll.x);
    split2(v0.z, v0.w, hh.y, ll.y);
    split2(v1.x, v1.y, hh.z, ll.z);
    split2(v1.z, v1.w, hh.w, ll.w);
    *(uint4*)(hi + i) = hh;
    *(uint4*)(lo + i) = ll;
}

// ---------------------------------------------------------------------------
// Kernel 1: QKV GEMM, bf16x3 HMMA, BK=32, 3-stage pipeline, 2 CTAs/SM.
// Epilogue scales the q output by log2(e) so attention can use exp2 directly.
// (Exact R14 kernel.)
// ---------------------------------------------------------------------------
#define S_ALO 8192
#define S_WHI 16384
#define S_WLO 24576
#define STAGE_B 32768
#define NST 3
#define GEMM_SMEM (NST * STAGE_B)   // 98304 -> 2 CTAs/SM
#define NIT (K_GEMM / 32)           // 32
#define EP_PITCH 68                 // u32 pitch for epilogue planes

__global__ __launch_bounds__(256, 2)
void qkv_gemm_tc(const float* __restrict__ bias)
{
    extern __shared__ char smb[];

    const int t    = threadIdx.x;
    const int bm   = blockIdx.y * 128;
    const int bn   = blockIdx.x * 128;
    const int lane = t & 31;
    const int wid  = t >> 5;
    const int g    = lane >> 2;
    const int t4   = lane & 3;
    const int m0   = (wid >> 1) * 32;
    const int wn   = wid & 1;
    const int n0   = wn * 64;

    float acc[2][8][4];
#pragma unroll
    for (int mt = 0; mt < 2; ++mt)
#pragma unroll
        for (int nt = 0; nt < 8; ++nt)
#pragma unroll
            for (int r = 0; r < 4; ++r) acc[mt][nt][r] = 0.f;

    auto issue = [&](int kt, int buf) {
        char* base = smb + buf * STAGE_B;
        const int k0 = kt * 32;
#pragma unroll
        for (int i = 0; i < 2; ++i) {                  // A hi/lo: 128 rows x 4 chunks
            const int id   = t + 256 * i;
            const int row  = id >> 2;
            const int c    = id & 3;
            const int srow = row & 63;
            const int ch   = (c + ((row >> 6) << 2)) ^ (srow & 7);
            const uint32_t doff = (uint32_t)(srow * 128 + ch * 16);
            const size_t  soff = (size_t)(bm + row) * K_GEMM + k0 + c * 8;
            CP_ASYNC16(smem_u32(base + doff), g_Ahi + soff);
            CP_ASYNC16(smem_u32(base + S_ALO + doff), g_Alo + soff);
        }
#pragma unroll
        for (int i = 0; i < 2; ++i) {                  // W hi/lo: 32 rows x 16 chunks
            const int id  = t + 256 * i;
            const int row = id >> 4;
            const int c   = id & 15;
            const uint32_t doff = (uint32_t)(row * 256 + ((c ^ (row & 7)) * 16));
            const size_t  soff = (size_t)(k0 + row) * N_GEMM + bn + c * 8;
            CP_ASYNC16(smem_u32(base + S_WHI + doff), g_Whi + soff);
            CP_ASYNC16(smem_u32(base + S_WLO + doff), g_Wlo + soff);
        }
    };

    issue(0, 0); CP_COMMIT();
    issue(1, 1); CP_COMMIT();

    for (int it = 0; it < NIT; ++it) {
        CP_WAIT1();
        __syncthreads();
        if (it + 2 < NIT) issue(it + 2, (it + 2) % NST);
        CP_COMMIT();

        const char* base = smb + (it % NST) * STAGE_B;
        const uint32_t aAhi = smem_u32(base);
        const uint32_t aAlo = smem_u32(base + S_ALO);
        const uint32_t aWhi = smem_u32(base + S_WHI);
        const uint32_t aWlo = smem_u32(base + S_WLO);

#pragma unroll
        for (int kk = 0; kk < 2; ++kk) {
            uint32_t aF[2][2][4];
            {
                const int mrow  = m0 + (lane & 15);
                const int srow0 = mrow & 63;
                const int hb    = (mrow >> 6) << 2;
                const int cb    = hb + 2 * kk + (lane >> 4);
                const uint32_t off0 = (uint32_t)(srow0 * 128 + ((cb ^ (srow0 & 7)) * 16));
                const int srow1 = (mrow + 16) & 63;
                const uint32_t off1 = (uint32_t)(srow1 * 128 + ((cb ^ (srow1 & 7)) * 16));
                LDSM4(aF[0][0], aAhi + off0);
                LDSM4(aF[0][1], aAhi + off1);
                LDSM4(aF[1][0], aAlo + off0);
                LDSM4(aF[1][1], aAlo + off1);
            }

            const int krow = kk * 16 + (lane & 15);
            const uint32_t wrow_off = (uint32_t)(krow * 256);
            const int bsel = lane >> 4;

#pragma unroll
            for (int nh = 0; nh < 2; ++nh) {
                uint32_t bF[2][4][2];
#pragma unroll
                for (int p = 0; p < 2; ++p) {
                    const int cc = wn * 8 + nh * 4 + 2 * p + bsel;
                    const uint32_t off = wrow_off + (uint32_t)((cc ^ (krow & 7)) * 16);
                    LDSM4T(bF[0][2 * p][0], bF[0][2 * p][1],
                           bF[0][2 * p + 1][0], bF[0][2 * p + 1][1], aWhi + off);
                    LDSM4T(bF[1][2 * p][0], bF[1][2 * p][1],
                           bF[1][2 * p + 1][0], bF[1][2 * p + 1][1], aWlo + off);
                }

#pragma unroll
                for (int nt = 0; nt < 4; ++nt)
#pragma unroll
                    for (int mt = 0; mt < 2; ++mt)
                        MMA16816(acc[mt][nh * 4 + nt],
                                 aF[0][mt][0], aF[0][mt][1], aF[0][mt][2], aF[0][mt][3],
                                 bF[0][nt][0], bF[0][nt][1]);
#pragma unroll
                for (int nt = 0; nt < 4; ++nt)
#pragma unroll
                    for (int mt = 0; mt < 2; ++mt)
                        MMA16816(acc[mt][nh * 4 + nt],
                                 aF[0][mt][0], aF[0][mt][1], aF[0][mt][2], aF[0][mt][3],
                                 bF[1][nt][0], bF[1][nt][1]);
#pragma unroll
                for (int nt = 0; nt < 4; ++nt)
#pragma unroll
                    for (int mt = 0; mt < 2; ++mt)
                        MMA16816(acc[mt][nh * 4 + nt],
                                 aF[1][mt][0], aF[1][mt][1], aF[1][mt][2], aF[1][mt][3],
                                 bF[0][nt][0], bF[0][nt][1]);
            }
        }
    }

    // ---- epilogue: bias (+ log2e scale for q) + split -> smem -> 16B stores
    CP_WAIT0();
    __syncthreads();

    const int which = bn >> 10;                      // CTA-uniform
    const float qscale = (which == 0) ? LOG2E : 1.0f;

    uint32_t* shi = (uint32_t*)smb;                 // 128 x EP_PITCH u32
    uint32_t* slo = shi + 128 * EP_PITCH;

#pragma unroll
    for (int mt = 0; mt < 2; ++mt) {
#pragma unroll
        for (int nt = 0; nt < 8; ++nt) {
            const int cc = bn + n0 + nt * 8 + 2 * t4;
            const float bx = __ldg(bias + cc);
            const float by = __ldg(bias + cc + 1);
            const int cidx = (n0 >> 1) + nt * 4 + t4;   // u32 column 0..63
#pragma unroll
            for (int half = 0; half < 2; ++half) {
                const int srow = m0 + mt * 16 + g + half * 8;
                uint32_t hv, lv;
                split2((acc[mt][nt][2 * half] + bx) * qscale,
                       (acc[mt][nt][2 * half + 1] + by) * qscale, hv, lv);
                shi[srow * EP_PITCH + cidx] = hv;
                slo[srow * EP_PITCH + cidx] = lv;
            }
        }
    }
    __syncthreads();

    __nv_bfloat16* dhi = (which == 0) ? g_qhi : (which == 1) ? g_khi : g_vhi;
    __nv_bfloat16* dlo = (which == 0) ? g_qlo : (which == 1) ? g_klo : g_vlo;

#pragma unroll
    for (int i = 0; i < 8; ++i) {
        const int u   = t + 256 * i;       // uint4 index 0..2047
        const int row = u >> 4;            // 0..127
        const int cu  = u & 15;            // 16B chunk within row
        uint4 vh = *(uint4*)(shi + row * EP_PITCH + cu * 4);
        uint4 vl = *(uint4*)(slo + row * EP_PITCH + cu * 4);
        const int mg = bm + row;
        const int b  = mg >> 12;
        const int s  = mg & 4095;
        const int n  = bn + cu * 8;
        const int h  = (n & 1023) >> 6;
        const int d0 = n & 63;
        const size_t off = ((size_t)(b * H_SZ + h) * S_SZ + s) * HD_SZ + d0;
        *(uint4*)(dhi + off) = vh;
        *(uint4*)(dlo + off) = vl;
    }
}

// ---------------------------------------------------------------------------
// Kernel 2: MMA flash attention, fixed-max softmax in exp2 domain (R14),
// with the l row-sum accumulation split into two independent partials to
// halve the serial FADD dependency chain.
// ---------------------------------------------------------------------------
#define SQ_HI 0
#define SQ_LO 16384
#define SK_HI 32768
#define SV_HI 65536
#define S_QSUM 98304
#define ATT_SMEM (98304 + 512)
#define MFIX2 (24.0f * 1.44269504088896340736f)   // 24 * log2(e)

__global__ __launch_bounds__(256, 2)
void attn_mma(float* __restrict__ out)
{
    extern __shared__ char smb[];
    const int w    = blockIdx.x;
    const int bh   = blockIdx.y;
    const int t    = threadIdx.x;
    const int lane = t & 31;
    const int wid  = t >> 5;
    const int g    = lane >> 2;
    const int t4   = lane & 3;
    const int r0   = wid * 16;
    const bool haspad = (w == 0) || (w == NW_SZ - 1);   // block-uniform

#pragma unroll
    for (int i = 0; i < 8; ++i) {
        const int id  = t + 256 * i;
        const int buf = id >> 10;
        const int idx = id & 1023;
        const int row = idx >> 3;
        const int c   = idx & 7;
        const int ph  = c ^ (row & 7);
        const __nv_bfloat16* src = buf ? g_qlo : g_qhi;
        CP_ASYNC16(smem_u32(smb + buf * 16384 + row * 128 + ph * 16),
                   src + ((size_t)bh * S_SZ + w * W_SZ + row) * HD_SZ + c * 8);
    }
    CP_COMMIT(); CP_WAIT0();
    __syncthreads();

    float* qsum = (float*)(smb + S_QSUM);
    if (haspad) {                       // qsum needed only for boundary windows
        if (t < 128) {
            float s = 0.f;
#pragma unroll
            for (int c = 0; c < 8; ++c) {
                const int ph = c ^ (t & 7);
                const uint32_t* hp = (const uint32_t*)(smb + SQ_HI + t * 128 + ph * 16);
                const uint32_t* lp = (const uint32_t*)(smb + SQ_LO + t * 128 + ph * 16);
#pragma unroll
                for (int e = 0; e < 4; ++e) {
                    float2 fh = __bfloat1622float2(*(const __nv_bfloat162*)&hp[e]);
                    float2 fl = __bfloat1622float2(*(const __nv_bfloat162*)&lp[e]);
                    s += fh.x + fh.y + fl.x + fl.y;
                }
            }
            qsum[t] = s;   // already in log2 domain (q pre-scaled)
        }
        __syncthreads();
    }

    // two independent partials per row-group to shorten the FADD chain
    float l0a = 0.f, l0b = 0.f, l1a = 0.f, l1b = 0.f;
    float O[8][4];
#pragma unroll
    for (int nd = 0; nd < 8; ++nd)
#pragma unroll
        for (int r = 0; r < 4; ++r) O[nd][r] = 0.f;

#pragma unroll
    for (int c = 0; c < 3; ++c) {
        const int wc = w - 1 + c;
        if (wc < 0 || wc >= NW_SZ) {
            const float e0 = exp2f(-qsum[r0 + g]     - MFIX2);
            const float e1 = exp2f(-qsum[r0 + g + 8] - MFIX2);
            l0a += e0 * 32.f;
            l1a += e1 * 32.f;
            const float q0 = e0 * 128.f;
            const float q1 = e1 * 128.f;
#pragma unroll
            for (int nd = 0; nd < 8; ++nd) {
                O[nd][0] -= q0; O[nd][1] -= q0;
                O[nd][2] -= q1; O[nd][3] -= q1;
            }
            continue;
        }

        __syncthreads();
#pragma unroll
        for (int i = 0; i < 16; ++i) {
            const int id  = t + 256 * i;
            const int buf = id >> 10;
            const int idx = id & 1023;
            const int row = idx >> 3;
            const int cc  = idx & 7;
            const int ph  = cc ^ (row & 7);
            const __nv_bfloat16* src = (buf == 0) ? g_khi : (buf == 1) ? g_klo
                                      : (buf == 2) ? g_vhi : g_vlo;
            CP_ASYNC16(smem_u32(smb + SK_HI + buf * 16384 + row * 128 + ph * 16),
                       src + ((size_t)bh * S_SZ + wc * W_SZ + row) * HD_SZ + cc * 8);
        }
        CP_COMMIT(); CP_WAIT0();
        __syncthreads();

        const int type = c;

#pragma unroll
        for (int half = 0; half < 2; ++half) {
            const int kb = 64 * half;
            int pmin = 0, pmax = 3;
            if (type == 0) {
                int d = r0 - kb; if (d < 0) d = 0;
                pmin = d >> 4;
                if (pmin > 3) continue;
            } else if (type == 2) {
                const int d = r0 - kb + 15;
                if (d < 0) continue;
                pmax = d >> 4; if (pmax > 3) pmax = 3;
            }

            float S[8][4];
#pragma unroll
            for (int j = 0; j < 8; ++j)
#pragma unroll
                for (int r = 0; r < 4; ++r) S[j][r] = 0.f;

#pragma unroll
            for (int ks = 0; ks < 4; ++ks) {
                uint32_t qh[4], ql[4];
                {
                    const int row = r0 + (lane & 15);
                    const int cc  = 2 * ks + (lane >> 4);
                    const int ph  = cc ^ (row & 7);
                    const uint32_t aq = smem_u32(smb + SQ_HI + row * 128 + ph * 16);
                    LDSM4(qh, aq);
                    LDSM4(ql, aq + 16384);
                }
#pragma unroll
                for (int p = 0; p < 4; ++p) {
                    if (p < pmin || p > pmax) continue;
                    uint32_t kh[4], kl[4];
                    {
                        const int row = kb + 16 * p + (lane & 7) + ((lane >> 4) << 3);
                        const int cc  = 2 * ks + ((lane >> 3) & 1);
                        const int ph  = cc ^ (row & 7);
                        const uint32_t ak = smem_u32(smb + SK_HI + row * 128 + ph * 16);
                        LDSM4(kh, ak);
                        LDSM4(kl, ak + 16384);
                    }
                    MMA16816(S[2 * p],     qh[0], qh[1], qh[2], qh[3], kh[0], kh[1]);
                    MMA16816(S[2 * p],     qh[0], qh[1], qh[2], qh[3], kl[0], kl[1]);
                    MMA16816(S[2 * p],     ql[0], ql[1], ql[2], ql[3], kh[0], kh[1]);
                    MMA16816(S[2 * p + 1], qh[0], qh[1], qh[2], qh[3], kh[2], kh[3]);
                    MMA16816(S[2 * p + 1], qh[0], qh[1], qh[2], qh[3], kl[2], kl[3]);
                    MMA16816(S[2 * p + 1], ql[0], ql[1], ql[2], ql[3], kh[2], kh[3]);
                }
            }

            // mask (skipped entirely for the own-window chunk)
            if (type != 1) {
#pragma unroll
                for (int j = 0; j < 8; ++j) {
                    if ((j >> 1) < pmin || (j >> 1) > pmax) continue;
#pragma unroll
                    for (int e = 0; e < 2; ++e) {
                        const int key = kb + 8 * j + 2 * t4 + e;
                        if (type == 0) {
                            if (key < r0 + g)     S[j][e]     = -CUDART_INF_F;
                            if (key < r0 + g + 8) S[j][2 + e] = -CUDART_INF_F;
                        } else {
                            if (key > r0 + g)     S[j][e]     = -CUDART_INF_F;
                            if (key > r0 + g + 8) S[j][2 + e] = -CUDART_INF_F;
                        }
                    }
                }
            }
            // exp2(s - MFIX2) + per-lane partial l (two independent chains)
#pragma unroll
            for (int j = 0; j < 8; ++j) {
                if ((j >> 1) < pmin || (j >> 1) > pmax) continue;
                S[j][0] = exp2f(S[j][0] - MFIX2);
                S[j][1] = exp2f(S[j][1] - MFIX2);
                S[j][2] = exp2f(S[j][2] - MFIX2);
                S[j][3] = exp2f(S[j][3] - MFIX2);
                if (j & 1) { l0b += S[j][0] + S[j][1]; l1b += S[j][2] + S[j][3]; }
                else       { l0a += S[j][0] + S[j][1]; l1a += S[j][2] + S[j][3]; }
            }

            // O += P V (bf16x3)
#pragma unroll
            for (int kt = 0; kt < 4; ++kt) {
                if (kt < pmin || kt > pmax) continue;
                uint32_t pah[4], pal[4];
                split2(S[2 * kt][0],     S[2 * kt][1],     pah[0], pal[0]);
                split2(S[2 * kt][2],     S[2 * kt][3],     pah[1], pal[1]);
                split2(S[2 * kt + 1][0], S[2 * kt + 1][1], pah[2], pal[2]);
                split2(S[2 * kt + 1][2], S[2 * kt + 1][3], pah[3], pal[3]);
#pragma unroll
                for (int dp = 0; dp < 4; ++dp) {
                    uint32_t vh[4], vl[4];
                    {
                        const int krow = kb + 16 * kt + (lane & 15);
                        const int cc   = 2 * dp + (lane >> 4);
                        const int ph   = cc ^ (krow & 7);
                        const uint32_t av = smem_u32(smb + SV_HI + krow * 128 + ph * 16);
                        LDSM4T(vh[0], vh[1], vh[2], vh[3], av);
                        LDSM4T(vl[0], vl[1], vl[2], vl[3], av + 16384);
                    }
                    MMA16816(O[2 * dp],     pah[0], pah[1], pah[2], pah[3], vh[0], vh[1]);
                    MMA16816(O[2 * dp],     pah[0], pah[1], pah[2], pah[3], vl[0], vl[1]);
                    MMA16816(O[2 * dp],     pal[0], pal[1], pal[2], pal[3], vh[0], vh[1]);
                    MMA16816(O[2 * dp + 1], pah[0], pah[1], pah[2], pah[3], vh[2], vh[3]);
                    MMA16816(O[2 * dp + 1], pah[0], pah[1], pah[2], pah[3], vl[2], vl[3]);
                    MMA16816(O[2 * dp + 1], pal[0], pal[1], pal[2], pal[3], vh[2], vh[3]);
                }
            }
        }
    }

    // merge partials, reduce over the t4 quad, normalize, write out
    float l0 = l0a + l0b;
    float l1 = l1a + l1b;
    l0 += __shfl_xor_sync(0xffffffffu, l0, 1);
    l0 += __shfl_xor_sync(0xffffffffu, l0, 2);
    l1 += __shfl_xor_sync(0xffffffffu, l1, 1);
    l1 += __shfl_xor_sync(0xffffffffu, l1, 2);

    const float inv0 = 1.f / l0, inv1 = 1.f / l1;
    const int b = bh >> 4, h = bh & 15;
    const int row0 = w * W_SZ + r0 + g;
    float* o0 = out + ((size_t)b * S_SZ + row0) * E_SZ + h * HD_SZ + 2 * t4;
    float* o1 = out + ((size_t)b * S_SZ + row0 + 8) * E_SZ + h * HD_SZ + 2 * t4;
#pragma unroll
    for (int nd = 0; nd < 8; ++nd) {
        float2 u; u.x = O[nd][0] * inv0; u.y = O[nd][1] * inv0;
        *(float2*)(o0 + 8 * nd) = u;
        float2 v; v.x = O[nd][2] * inv1; v.y = O[nd][3] * inv1;
        *(float2*)(o1 + 8 * nd) = v;
    }
}

// ---------------------------------------------------------------------------
extern "C" void kernel_launch(void* const* d_in, const int* in_sizes, int n_in,
                              void* d_out, int out_size)
{
    const float* x    = (const float*)d_in[0];   // [4, 4096, 1024]
    const float* wqkv = (const float*)d_in[1];   // [1024, 3072]
    const float* bqkv = (const float*)d_in[2];   // [3072]
    float* out = (float*)d_out;                  // [4, 4096, 1024]

    split_all_kernel<<<A_SPLIT_BLOCKS + W_SPLIT_BLOCKS, 256>>>(x, wqkv);

    cudaFuncSetAttribute(qkv_gemm_tc,
                         cudaFuncAttributeMaxDynamicSharedMemorySize, GEMM_SMEM);
    dim3 g1(N_GEMM / 128, M_GEMM / 128);         // (24, 128)
    qkv_gemm_tc<<<g1, 256, GEMM_SMEM>>>(bqkv);

    cudaFuncSetAttribute(attn_mma,
                         cudaFuncAttributeMaxDynamicSharedMemorySize, ATT_SMEM);
    dim3 g2(NW_SZ, BH_SZ);                       // (32, 64)
    attn_mma<<<g2, 256, ATT_SMEM>>>(out);
}

// round 17
// speedup vs baseline: 1.0043x; 1.0040x over previous
#include <cuda_runtime.h>
#include <cuda_bf16.h>
#include <math_constants.h>
#include <stdint.h>

// Problem constants
#define B_SZ 4
#define S_SZ 4096
#define E_SZ 1024
#define H_SZ 16
#define HD_SZ 64
#define W_SZ 128
#define NW_SZ 32
#define BH_SZ (B_SZ * H_SZ)      // 64
#define M_GEMM (B_SZ * S_SZ)     // 16384
#define N_GEMM (3 * E_SZ)        // 3072
#define K_GEMM E_SZ              // 1024
#define LOG2E 1.44269504088896340736f

// GEMM input splits. A: [M,K] K-major. W: [K,N] row-major.
__device__ __nv_bfloat16 g_Ahi[M_GEMM * K_GEMM];
__device__ __nv_bfloat16 g_Alo[M_GEMM * K_GEMM];
__device__ __nv_bfloat16 g_Whi[K_GEMM * N_GEMM];
__device__ __nv_bfloat16 g_Wlo[K_GEMM * N_GEMM];
// q/k/v head layout [BH, S, HD], bf16 hi/lo.  NOTE: q is pre-scaled by log2(e).
__device__ __nv_bfloat16 g_qhi[BH_SZ * S_SZ * HD_SZ];
__device__ __nv_bfloat16 g_qlo[BH_SZ * S_SZ * HD_SZ];
__device__ __nv_bfloat16 g_khi[BH_SZ * S_SZ * HD_SZ];
__device__ __nv_bfloat16 g_klo[BH_SZ * S_SZ * HD_SZ];
__device__ __nv_bfloat16 g_vhi[BH_SZ * S_SZ * HD_SZ];
__device__ __nv_bfloat16 g_vlo[BH_SZ * S_SZ * HD_SZ];

// ---------------------------------------------------------------------------
// helpers
// ---------------------------------------------------------------------------
__device__ __forceinline__ void split2(float x, float y, uint32_t& hi, uint32_t& lo)
{
    __nv_bfloat16 hx = __float2bfloat16(x);
    __nv_bfloat16 hy = __float2bfloat16(y);
    float rx = x - __bfloat162float(hx);
    float ry = y - __bfloat162float(hy);
    __nv_bfloat162 h; h.x = hx; h.y = hy;
    __nv_bfloat162 l; l.x = __float2bfloat16(rx); l.y = __float2bfloat16(ry);
    hi = *reinterpret_cast<uint32_t*>(&h);
    lo = *reinterpret_cast<uint32_t*>(&l);
}

__device__ __forceinline__ uint32_t smem_u32(const void* p)
{
    return (uint32_t)__cvta_generic_to_shared(p);
}

#define CP_ASYNC16(dst_u32, src_ptr)                                            \
    asm volatile("cp.async.cg.shared.global [%0], [%1], 16;\n"                  \
                 :: "r"(dst_u32), "l"(__cvta_generic_to_global(src_ptr)))
#define CP_COMMIT() asm volatile("cp.async.commit_group;\n" ::)
#define CP_WAIT1()  asm volatile("cp.async.wait_group 1;\n" ::)
#define CP_WAIT0()  asm volatile("cp.async.wait_group 0;\n" ::)

#define LDSM4(R, ADDR)                                                          \
    asm volatile("ldmatrix.sync.aligned.m8n8.x4.shared.b16 {%0,%1,%2,%3}, [%4];"\
                 : "=r"(R[0]), "=r"(R[1]), "=r"(R[2]), "=r"(R[3]) : "r"(ADDR))
#define LDSM4T(R0, R1, R2, R3, ADDR)                                            \
    asm volatile("ldmatrix.sync.aligned.m8n8.x4.trans.shared.b16 {%0,%1,%2,%3}, [%4];" \
                 : "=r"(R0), "=r"(R1), "=r"(R2), "=r"(R3) : "r"(ADDR))

#define MMA16816(ACC, A0, A1, A2, A3, B0, B1)                                   \
    asm volatile(                                                               \
        "mma.sync.aligned.m16n8k16.row.col.f32.bf16.bf16.f32 "                  \
        "{%0,%1,%2,%3}, {%4,%5,%6,%7}, {%8,%9}, {%0,%1,%2,%3};\n"               \
        : "+f"(ACC[0]), "+f"(ACC[1]), "+f"(ACC[2]), "+f"(ACC[3])                \
        : "r"(A0), "r"(A1), "r"(A2), "r"(A3), "r"(B0), "r"(B1))

// ---------------------------------------------------------------------------
// Kernel 0: fused fp32 -> bf16 hi/lo splits for A and W (one launch).
// 8 elements per thread (at HBM roofline).
// ---------------------------------------------------------------------------
#define A_SPLIT_BLOCKS (M_GEMM * K_GEMM / 8 / 256)   // 8192
#define W_SPLIT_BLOCKS (K_GEMM * N_GEMM / 8 / 256)   // 1536

__global__ __launch_bounds__(256)
void split_all_kernel(const float* __restrict__ x, const float* __restrict__ w)
{
    const int bid = blockIdx.x;
    const float* src;
    __nv_bfloat16 *hi, *lo;
    int i;
    if (bid < A_SPLIT_BLOCKS) {
        src = x; hi = g_Ahi; lo = g_Alo;
        i = (bid * 256 + threadIdx.x) * 8;
    } else {
        src = w; hi = g_Whi; lo = g_Wlo;
        i = ((bid - A_SPLIT_BLOCKS) * 256 + threadIdx.x) * 8;
    }
    float4 v0 = *(const float4*)(src + i);
    float4 v1 = *(const float4*)(src + i + 4);
    uint4 hh, ll;
    split2(v0.x, v0.y, hh.x, ll.x);
    split2(v0.z, v0.w, hh.y, ll.y);
    split2(v1.x, v1.y, hh.z, ll.z);
    split2(v1.z, v1.w, hh.w, ll.w);
    *(uint4*)(hi + i) = hh;
    *(uint4*)(lo + i) = ll;
}

// ---------------------------------------------------------------------------
// Kernel 1: QKV GEMM, bf16x3 HMMA, BK=32, 3-stage pipeline, 2 CTAs/SM.
// Epilogue scales the q output by log2(e) so attention can use exp2 directly.
// ---------------------------------------------------------------------------
#define S_ALO 8192
#define S_WHI 16384
#define S_WLO 24576
#define STAGE_B 32768
#define NST 3
#define GEMM_SMEM (NST * STAGE_B)   // 98304 -> 2 CTAs/SM
#define NIT (K_GEMM / 32)           // 32
#define EP_PITCH 68                 // u32 pitch for epilogue planes

__global__ __launch_bounds__(256, 2)
void qkv_gemm_tc(const float* __restrict__ bias)
{
    extern __shared__ char smb[];

    const int t    = threadIdx.x;
    const int bm   = blockIdx.y * 128;
    const int bn   = blockIdx.x * 128;
    const int lane = t & 31;
    const int wid  = t >> 5;
    const int g    = lane >> 2;
    const int t4   = lane & 3;
    const int m0   = (wid >> 1) * 32;
    const int wn   = wid & 1;
    const int n0   = wn * 64;

    float acc[2][8][4];
#pragma unroll
    for (int mt = 0; mt < 2; ++mt)
#pragma unroll
        for (int nt = 0; nt < 8; ++nt)
#pragma unroll
            for (int r = 0; r < 4; ++r) acc[mt][nt][r] = 0.f;

    auto issue = [&](int kt, int buf) {
        char* base = smb + buf * STAGE_B;
        const int k0 = kt * 32;
#pragma unroll
        for (int i = 0; i < 2; ++i) {                  // A hi/lo: 128 rows x 4 chunks
            const int id   = t + 256 * i;
            const int row  = id >> 2;
            const int c    = id & 3;
            const int srow = row & 63;
            const int ch   = (c + ((row >> 6) << 2)) ^ (srow & 7);
            const uint32_t doff = (uint32_t)(srow * 128 + ch * 16);
            const size_t  soff = (size_t)(bm + row) * K_GEMM + k0 + c * 8;
            CP_ASYNC16(smem_u32(base + doff), g_Ahi + soff);
            CP_ASYNC16(smem_u32(base + S_ALO + doff), g_Alo + soff);
        }
#pragma unroll
        for (int i = 0; i < 2; ++i) {                  // W hi/lo: 32 rows x 16 chunks
            const int id  = t + 256 * i;
            const int row = id >> 4;
            const int c   = id & 15;
            const uint32_t doff = (uint32_t)(row * 256 + ((c ^ (row & 7)) * 16));
            const size_t  soff = (size_t)(k0 + row) * N_GEMM + bn + c * 8;
            CP_ASYNC16(smem_u32(base + S_WHI + doff), g_Whi + soff);
            CP_ASYNC16(smem_u32(base + S_WLO + doff), g_Wlo + soff);
        }
    };

    issue(0, 0); CP_COMMIT();
    issue(1, 1); CP_COMMIT();

    for (int it = 0; it < NIT; ++it) {
        CP_WAIT1();
        __syncthreads();
        if (it + 2 < NIT) issue(it + 2, (it + 2) % NST);
        CP_COMMIT();

        const char* base = smb + (it % NST) * STAGE_B;
        const uint32_t aAhi = smem_u32(base);
        const uint32_t aAlo = smem_u32(base + S_ALO);
        const uint32_t aWhi = smem_u32(base + S_WHI);
        const uint32_t aWlo = smem_u32(base + S_WLO);

#pragma unroll
        for (int kk = 0; kk < 2; ++kk) {
            uint32_t aF[2][2][4];
            {
                const int mrow  = m0 + (lane & 15);
                const int srow0 = mrow & 63;
                const int hb    = (mrow >> 6) << 2;
                const int cb    = hb + 2 * kk + (lane >> 4);
                const uint32_t off0 = (uint32_t)(srow0 * 128 + ((cb ^ (srow0 & 7)) * 16));
                const int srow1 = (mrow + 16) & 63;
                const uint32_t off1 = (uint32_t)(srow1 * 128 + ((cb ^ (srow1 & 7)) * 16));
                LDSM4(aF[0][0], aAhi + off0);
                LDSM4(aF[0][1], aAhi + off1);
                LDSM4(aF[1][0], aAlo + off0);
                LDSM4(aF[1][1], aAlo + off1);
            }

            const int krow = kk * 16 + (lane & 15);
            const uint32_t wrow_off = (uint32_t)(krow * 256);
            const int bsel = lane >> 4;

#pragma unroll
            for (int nh = 0; nh < 2; ++nh) {
                uint32_t bF[2][4][2];
#pragma unroll
                for (int p = 0; p < 2; ++p) {
                    const int cc = wn * 8 + nh * 4 + 2 * p + bsel;
                    const uint32_t off = wrow_off + (uint32_t)((cc ^ (krow & 7)) * 16);
                    LDSM4T(bF[0][2 * p][0], bF[0][2 * p][1],
                           bF[0][2 * p + 1][0], bF[0][2 * p + 1][1], aWhi + off);
                    LDSM4T(bF[1][2 * p][0], bF[1][2 * p][1],
                           bF[1][2 * p + 1][0], bF[1][2 * p + 1][1], aWlo + off);
                }

#pragma unroll
                for (int nt = 0; nt < 4; ++nt)
#pragma unroll
                    for (int mt = 0; mt < 2; ++mt)
                        MMA16816(acc[mt][nh * 4 + nt],
                                 aF[0][mt][0], aF[0][mt][1], aF[0][mt][2], aF[0][mt][3],
                                 bF[0][nt][0], bF[0][nt][1]);
#pragma unroll
                for (int nt = 0; nt < 4; ++nt)
#pragma unroll
                    for (int mt = 0; mt < 2; ++mt)
                        MMA16816(acc[mt][nh * 4 + nt],
                                 aF[0][mt][0], aF[0][mt][1], aF[0][mt][2], aF[0][mt][3],
                                 bF[1][nt][0], bF[1][nt][1]);
#pragma unroll
                for (int nt = 0; nt < 4; ++nt)
#pragma unroll
                    for (int mt = 0; mt < 2; ++mt)
                        MMA16816(acc[mt][nh * 4 + nt],
                                 aF[1][mt][0], aF[1][mt][1], aF[1][mt][2], aF[1][mt][3],
                                 bF[0][nt][0], bF[0][nt][1]);
            }
        }
    }

    // ---- epilogue: bias (+ log2e scale for q) + split -> smem -> 16B stores
    CP_WAIT0();
    __syncthreads();

    const int which = bn >> 10;                      // CTA-uniform
    const float qscale = (which == 0) ? LOG2E : 1.0f;

    uint32_t* shi = (uint32_t*)smb;                 // 128 x EP_PITCH u32
    uint32_t* slo = shi + 128 * EP_PITCH;

#pragma unroll
    for (int mt = 0; mt < 2; ++mt) {
#pragma unroll
        for (int nt = 0; nt < 8; ++nt) {
            const int cc = bn + n0 + nt * 8 + 2 * t4;
            const float bx = __ldg(bias + cc);
            const float by = __ldg(bias + cc + 1);
            const int cidx = (n0 >> 1) + nt * 4 + t4;   // u32 column 0..63
#pragma unroll
            for (int half = 0; half < 2; ++half) {
                const int srow = m0 + mt * 16 + g + half * 8;
                uint32_t hv, lv;
                split2((acc[mt][nt][2 * half] + bx) * qscale,
                       (acc[mt][nt][2 * half + 1] + by) * qscale, hv, lv);
                shi[srow * EP_PITCH + cidx] = hv;
                slo[srow * EP_PITCH + cidx] = lv;
            }
        }
    }
    __syncthreads();

    __nv_bfloat16* dhi = (which == 0) ? g_qhi : (which == 1) ? g_khi : g_vhi;
    __nv_bfloat16* dlo = (which == 0) ? g_qlo : (which == 1) ? g_klo : g_vlo;

#pragma unroll
    for (int i = 0; i < 8; ++i) {
        const int u   = t + 256 * i;       // uint4 index 0..2047
        const int row = u >> 4;            // 0..127
        const int cu  = u & 15;            // 16B chunk within row
        uint4 vh = *(uint4*)(shi + row * EP_PITCH + cu * 4);
        uint4 vl = *(uint4*)(slo + row * EP_PITCH + cu * 4);
        const int mg = bm + row;
        const int b  = mg >> 12;
        const int s  = mg & 4095;
        const int n  = bn + cu * 8;
        const int h  = (n & 1023) >> 6;
        const int d0 = n & 63;
        const size_t off = ((size_t)(b * H_SZ + h) * S_SZ + s) * HD_SZ + d0;
        *(uint4*)(dhi + off) = vh;
        *(uint4*)(dlo + off) = vl;
    }
}

// ---------------------------------------------------------------------------
// Kernel 2: MMA flash attention, fixed-max softmax in exp2 domain.
// q pre-scaled by log2(e) => P = exp2(S - MFIX2). qsum phase only for
// boundary windows; mask chain skipped for the own-window chunk.
// ---------------------------------------------------------------------------
#define SQ_HI 0
#define SQ_LO 16384
#define SK_HI 32768
#define SV_HI 65536
#define S_QSUM 98304
#define ATT_SMEM (98304 + 512)
#define MFIX2 (24.0f * 1.44269504088896340736f)   // 24 * log2(e)

__global__ __launch_bounds__(256, 2)
void attn_mma(float* __restrict__ out)
{
    extern __shared__ char smb[];
    const int w    = blockIdx.x;
    const int bh   = blockIdx.y;
    const int t    = threadIdx.x;
    const int lane = t & 31;
    const int wid  = t >> 5;
    const int g    = lane >> 2;
    const int t4   = lane & 3;
    const int r0   = wid * 16;
    const bool haspad = (w == 0) || (w == NW_SZ - 1);   // block-uniform

#pragma unroll
    for (int i = 0; i < 8; ++i) {
        const int id  = t + 256 * i;
        const int buf = id >> 10;
        const int idx = id & 1023;
        const int row = idx >> 3;
        const int c   = idx & 7;
        const int ph  = c ^ (row & 7);
        const __nv_bfloat16* src = buf ? g_qlo : g_qhi;
        CP_ASYNC16(smem_u32(smb + buf * 16384 + row * 128 + ph * 16),
                   src + ((size_t)bh * S_SZ + w * W_SZ + row) * HD_SZ + c * 8);
    }
    CP_COMMIT(); CP_WAIT0();
    __syncthreads();

    float* qsum = (float*)(smb + S_QSUM);
    if (haspad) {                       // qsum needed only for boundary windows
        if (t < 128) {
            float s = 0.f;
#pragma unroll
            for (int c = 0; c < 8; ++c) {
                const int ph = c ^ (t & 7);
                const uint32_t* hp = (const uint32_t*)(smb + SQ_HI + t * 128 + ph * 16);
                const uint32_t* lp = (const uint32_t*)(smb + SQ_LO + t * 128 + ph * 16);
#pragma unroll
                for (int e = 0; e < 4; ++e) {
                    float2 fh = __bfloat1622float2(*(const __nv_bfloat162*)&hp[e]);
                    float2 fl = __bfloat1622float2(*(const __nv_bfloat162*)&lp[e]);
                    s += fh.x + fh.y + fl.x + fl.y;
                }
            }
            qsum[t] = s;   // already in log2 domain (q pre-scaled)
        }
        __syncthreads();
    }

    float l0 = 0.f, l1 = 0.f;        // per-lane partial row sums
    float O[8][4];
#pragma unroll
    for (int nd = 0; nd < 8; ++nd)
#pragma unroll
        for (int r = 0; r < 4; ++r) O[nd][r] = 0.f;

#pragma unroll
    for (int c = 0; c < 3; ++c) {
        const int wc = w - 1 + c;
        if (wc < 0 || wc >= NW_SZ) {
            const float e0 = exp2f(-qsum[r0 + g]     - MFIX2);
            const float e1 = exp2f(-qsum[r0 + g + 8] - MFIX2);
            l0 += e0 * 32.f;
            l1 += e1 * 32.f;
            const float q0 = e0 * 128.f;
            const float q1 = e1 * 128.f;
#pragma unroll
            for (int nd = 0; nd < 8; ++nd) {
                O[nd][0] -= q0; O[nd][1] -= q0;
                O[nd][2] -= q1; O[nd][3] -= q1;
            }
            continue;
        }

        __syncthreads();
#pragma unroll
        for (int i = 0; i < 16; ++i) {
            const int id  = t + 256 * i;
            const int buf = id >> 10;
            const int idx = id & 1023;
            const int row = idx >> 3;
            const int cc  = idx & 7;
            const int ph  = cc ^ (row & 7);
            const __nv_bfloat16* src = (buf == 0) ? g_khi : (buf == 1) ? g_klo
                                      : (buf == 2) ? g_vhi : g_vlo;
            CP_ASYNC16(smem_u32(smb + SK_HI + buf * 16384 + row * 128 + ph * 16),
                       src + ((size_t)bh * S_SZ + wc * W_SZ + row) * HD_SZ + cc * 8);
        }
        CP_COMMIT(); CP_WAIT0();
        __syncthreads();

        const int type = c;

#pragma unroll
        for (int half = 0; half < 2; ++half) {
            const int kb = 64 * half;
            int pmin = 0, pmax = 3;
            if (type == 0) {
                int d = r0 - kb; if (d < 0) d = 0;
                pmin = d >> 4;
                if (pmin > 3) continue;
            } else if (type == 2) {
                const int d = r0 - kb + 15;
                if (d < 0) continue;
                pmax = d >> 4; if (pmax > 3) pmax = 3;
            }

            float S[8][4];
#pragma unroll
            for (int j = 0; j < 8; ++j)
#pragma unroll
                for (int r = 0; r < 4; ++r) S[j][r] = 0.f;

#pragma unroll
            for (int ks = 0; ks < 4; ++ks) {
                uint32_t qh[4], ql[4];
                {
                    const int row = r0 + (lane & 15);
                    const int cc  = 2 * ks + (lane >> 4);
                    const int ph  = cc ^ (row & 7);
                    const uint32_t aq = smem_u32(smb + SQ_HI + row * 128 + ph * 16);
                    LDSM4(qh, aq);
                    LDSM4(ql, aq + 16384);
                }
#pragma unroll
                for (int p = 0; p < 4; ++p) {
                    if (p < pmin || p > pmax) continue;
                    uint32_t kh[4], kl[4];
                    {
                        const int row = kb + 16 * p + (lane & 7) + ((lane >> 4) << 3);
                        const int cc  = 2 * ks + ((lane >> 3) & 1);
                        const int ph  = cc ^ (row & 7);
                        const uint32_t ak = smem_u32(smb + SK_HI + row * 128 + ph * 16);
                        LDSM4(kh, ak);
                        LDSM4(kl, ak + 16384);
                    }
                    MMA16816(S[2 * p],     qh[0], qh[1], qh[2], qh[3], kh[0], kh[1]);
                    MMA16816(S[2 * p],     qh[0], qh[1], qh[2], qh[3], kl[0], kl[1]);
                    MMA16816(S[2 * p],     ql[0], ql[1], ql[2], ql[3], kh[0], kh[1]);
                    MMA16816(S[2 * p + 1], qh[0], qh[1], qh[2], qh[3], kh[2], kh[3]);
                    MMA16816(S[2 * p + 1], qh[0], qh[1], qh[2], qh[3], kl[2], kl[3]);
                    MMA16816(S[2 * p + 1], ql[0], ql[1], ql[2], ql[3], kh[2], kh[3]);
                }
            }

            // mask (skipped entirely for the own-window chunk)
            if (type != 1) {
#pragma unroll
                for (int j = 0; j < 8; ++j) {
                    if ((j >> 1) < pmin || (j >> 1) > pmax) continue;
#pragma unroll
                    for (int e = 0; e < 2; ++e) {
                        const int key = kb + 8 * j + 2 * t4 + e;
                        if (type == 0) {
                            if (key < r0 + g)     S[j][e]     = -CUDART_INF_F;
                            if (key < r0 + g + 8) S[j][2 + e] = -CUDART_INF_F;
                        } else {
                            if (key > r0 + g)     S[j][e]     = -CUDART_INF_F;
                            if (key > r0 + g + 8) S[j][2 + e] = -CUDART_INF_F;
                        }
                    }
                }
            }
            // exp2(s - MFIX2) + per-lane partial l
#pragma unroll
            for (int j = 0; j < 8; ++j) {
                if ((j >> 1) < pmin || (j >> 1) > pmax) continue;
#pragma unroll
                for (int e = 0; e < 2; ++e) {
                    S[j][e]     = exp2f(S[j][e]     - MFIX2); l0 += S[j][e];
                    S[j][2 + e] = exp2f(S[j][2 + e] - MFIX2); l1 += S[j][2 + e];
                }
            }

            // O += P V (bf16x3)
#pragma unroll
            for (int kt = 0; kt < 4; ++kt) {
                if (kt < pmin || kt > pmax) continue;
                uint32_t pah[4], pal[4];
                split2(S[2 * kt][0],     S[2 * kt][1],     pah[0], pal[0]);
                split2(S[2 * kt][2],     S[2 * kt][3],     pah[1], pal[1]);
                split2(S[2 * kt + 1][0], S[2 * kt + 1][1], pah[2], pal[2]);
                split2(S[2 * kt + 1][2], S[2 * kt + 1][3], pah[3], pal[3]);
#pragma unroll
                for (int dp = 0; dp < 4; ++dp) {
                    uint32_t vh[4], vl[4];
                    {
                        const int krow = kb + 16 * kt + (lane & 15);
                        const int cc   = 2 * dp + (lane >> 4);
                        const int ph   = cc ^ (krow & 7);
                        const uint32_t av = smem_u32(smb + SV_HI + krow * 128 + ph * 16);
                        LDSM4T(vh[0], vh[1], vh[2], vh[3], av);
                        LDSM4T(vl[0], vl[1], vl[2], vl[3], av + 16384);
                    }
                    MMA16816(O[2 * dp],     pah[0], pah[1], pah[2], pah[3], vh[0], vh[1]);
                    MMA16816(O[2 * dp],     pah[0], pah[1], pah[2], pah[3], vl[0], vl[1]);
                    MMA16816(O[2 * dp],     pal[0], pal[1], pal[2], pal[3], vh[0], vh[1]);
                    MMA16816(O[2 * dp + 1], pah[0], pah[1], pah[2], pah[3], vh[2], vh[3]);
                    MMA16816(O[2 * dp + 1], pah[0], pah[1], pah[2], pah[3], vl[2], vl[3]);
                    MMA16816(O[2 * dp + 1], pal[0], pal[1], pal[2], pal[3], vh[2], vh[3]);
                }
            }
        }
    }

    // reduce l over the t4 quad, normalize, write out
    l0 += __shfl_xor_sync(0xffffffffu, l0, 1);
    l0 += __shfl_xor_sync(0xffffffffu, l0, 2);
    l1 += __shfl_xor_sync(0xffffffffu, l1, 1);
    l1 += __shfl_xor_sync(0xffffffffu, l1, 2);

    const float inv0 = 1.f / l0, inv1 = 1.f / l1;
    const int b = bh >> 4, h = bh & 15;
    const int row0 = w * W_SZ + r0 + g;
    float* o0 = out + ((size_t)b * S_SZ + row0) * E_SZ + h * HD_SZ + 2 * t4;
    float* o1 = out + ((size_t)b * S_SZ + row0 + 8) * E_SZ + h * HD_SZ + 2 * t4;
#pragma unroll
    for (int nd = 0; nd < 8; ++nd) {
        float2 u; u.x = O[nd][0] * inv0; u.y = O[nd][1] * inv0;
        *(float2*)(o0 + 8 * nd) = u;
        float2 v; v.x = O[nd][2] * inv1; v.y = O[nd][3] * inv1;
        *(float2*)(o1 + 8 * nd) = v;
    }
}

// ---------------------------------------------------------------------------
extern "C" void kernel_launch(void* const* d_in, const int* in_sizes, int n_in,
                              void* d_out, int out_size)
{
    const float* x    = (const float*)d_in[0];   // [4, 4096, 1024]
    const float* wqkv = (const float*)d_in[1];   // [1024, 3072]
    const float* bqkv = (const float*)d_in[2];   // [3072]
    float* out = (float*)d_out;                  // [4, 4096, 1024]

    split_all_kernel<<<A_SPLIT_BLOCKS + W_SPLIT_BLOCKS, 256>>>(x, wqkv);

    cudaFuncSetAttribute(qkv_gemm_tc,
                         cudaFuncAttributeMaxDynamicSharedMemorySize, GEMM_SMEM);
    dim3 g1(N_GEMM / 128, M_GEMM / 128);         // (24, 128)
    qkv_gemm_tc<<<g1, 256, GEMM_SMEM>>>(bqkv);

    cudaFuncSetAttribute(attn_mma,
                         cudaFuncAttributeMaxDynamicSharedMemorySize, ATT_SMEM);
    dim3 g2(NW_SZ, BH_SZ);                       // (32, 64)
    attn_mma<<<g2, 256, ATT_SMEM>>>(out);
}